// round 5
// baseline (speedup 1.0000x reference)
#include <cuda_runtime.h>

#define NR 8192
#define NT 8192
#define RB 64
#define CB 64
#define GRIDC 592          // 148 SMs * 4 CTAs

// Device scratch (zero-init; k_final restores zeros after consuming)
__device__ float g_B[RB * CB];
__device__ int   g_rcum[RB + 1];
__device__ int   g_ccum[CB + 1];

// ---------------------------------------------------------------------------
// The 256 MB pass. Persistent-ish CTAs, each owning a CONTIGUOUS chunk of
// ~14 rows. Warp w owns cols [1024w, 1024w+1024). Coalesced float4 LDG,
// reduced directly from registers with a warp-uniform window walk:
//   - window (128 cols) fully inside current col-block -> 3-FADD tree add
//   - boundary window -> predicated split + fire-and-forget smem atomic into
//     bank-spread per-lane table wl[cb][lane] (no shfl chains, no stalls)
// wl accumulates across all rows of one row-block, drained to g_B once per
// rb segment. No smem data staging at all -> L1 pipe belongs to the LDGs.
// ---------------------------------------------------------------------------
__global__ __launch_bounds__(256) void k_colsum(const float* __restrict__ X,
                                                const int* __restrict__ row_ids,
                                                const int* __restrict__ col_ids) {
    __shared__ int   scum[CB + 1];
    __shared__ float wl[CB][33];      // bank-spread: bank(cb,l) = (cb+l)%32

    const int tid  = threadIdx.x;
    const int lane = tid & 31;
    const int w    = tid >> 5;

    // col-block boundaries via transition scan over sorted ids
    for (int i = tid; i < NT; i += 256) {
        int cur  = col_ids[i];
        int prev = i ? col_ids[i - 1] : -1;
        for (int b = prev; b < cur; b++) scum[b + 1] = i;
    }
    if (tid == 0) { scum[0] = 0; scum[CB] = NT; }
    for (int i = tid; i < CB * 33; i += 256) ((float*)wl)[i] = 0.0f;
    __syncthreads();

    // CTA 0 additionally publishes the cumsums for k_final (overlapped work)
    if (blockIdx.x == 0) {
        for (int i = tid; i < NR; i += 256) {
            int cur  = row_ids[i];
            int prev = i ? row_ids[i - 1] : -1;
            for (int b = prev; b < cur; b++) g_rcum[b + 1] = i;
        }
        if (tid == 0) { g_rcum[0] = 0; g_rcum[RB] = NR; }
        if (tid <= CB) g_ccum[tid] = scum[tid];
    }

    // block containing this warp's first column (warp-uniform)
    int lo = 0, hi = CB;
    const int base_w = w << 10;
    while (lo < hi) {
        int mid = (lo + hi + 1) >> 1;
        if (scum[mid] <= base_w) lo = mid; else hi = mid - 1;
    }
    const int cb0 = lo;

    const int r0 = (int)(((long long)blockIdx.x * NR) / GRIDC);
    const int r1 = (int)(((long long)(blockIdx.x + 1) * NR) / GRIDC);

    int r = r0;
    while (r < r1) {
        const int rb = row_ids[r];               // uniform broadcast load
        // ---- process all rows of this rb segment ----
        do {
            const float4* Xr = (const float4*)X + (size_t)r * (NT / 4);
            int   cb  = cb0;
            int   nb  = scum[cb0 + 1];
            float acc = 0.0f;
#pragma unroll
            for (int s = 0; s < 8; s++) {
                const float4 q  = Xr[(w << 8) + (s << 5) + lane];  // coalesced
                const int    W0 = base_w + (s << 7);
                const int    c  = W0 + (lane << 2);
                if (nb >= W0 + 128) {
                    acc += (q.x + q.y) + (q.z + q.w);
                } else {
                    int L = W0;
                    while (true) {                 // warp-uniform walk
                        int e = min(nb, W0 + 128);
                        acc += ((c + 0 >= L && c + 0 < e) ? q.x : 0.0f)
                             + ((c + 1 >= L && c + 1 < e) ? q.y : 0.0f)
                             + ((c + 2 >= L && c + 2 < e) ? q.z : 0.0f)
                             + ((c + 3 >= L && c + 3 < e) ? q.w : 0.0f);
                        if (nb >= W0 + 128) break;
                        atomicAdd(&wl[cb][lane], acc);   // fire-and-forget
                        acc = 0.0f;
                        L = nb;
                        cb++;
                        nb = scum[cb + 1];
                    }
                }
            }
            atomicAdd(&wl[cb][lane], acc);        // row-end flush (last block)
            r++;
        } while (r < r1 && row_ids[r] == rb);     // uniform condition

        // ---- drain wl -> g_B[rb][*] (rare: ~1-2x per chunk) ----
        __syncthreads();
        if (tid < CB) {
            float s = 0.0f;
#pragma unroll
            for (int j = 0; j < 32; j++) s += wl[tid][j];   // conflict-free
            if (s != 0.0f) atomicAdd(&g_B[rb * CB + tid], s);
        }
        __syncthreads();
        for (int i = tid; i < CB * 33; i += 256) ((float*)wl)[i] = 0.0f;
        __syncthreads();
    }
}

// ---------------------------------------------------------------------------
// Tiny final: block mean from g_B + published cumsums, 1->3->3->1 ReLU MLP,
// sigmoid, cumsum tails; re-zero g_B for the next graph replay.
// Grid: 64 CTAs x 64 threads.
// ---------------------------------------------------------------------------
__global__ void k_final(const float* __restrict__ W1, const float* __restrict__ b1,
                        const float* __restrict__ W2, const float* __restrict__ b2,
                        const float* __restrict__ W3, const float* __restrict__ b3,
                        float* __restrict__ out, int out_size) {
    const int rb = blockIdx.x;
    const int cb = threadIdx.x;

    const float s      = g_B[rb * CB + cb];
    const float rcount = (float)(g_rcum[rb + 1] - g_rcum[rb]);
    const float ccount = (float)(g_ccum[cb + 1] - g_ccum[cb]);
    const float x      = s / (rcount * ccount);

    float h1[3], h2[3];
#pragma unroll
    for (int k = 0; k < 3; k++) h1[k] = fmaxf(x * W1[k] + b1[k], 0.0f);
#pragma unroll
    for (int j = 0; j < 3; j++) {
        float z = b2[j];
#pragma unroll
        for (int k = 0; k < 3; k++) z += h1[k] * W2[k * 3 + j];
        h2[j] = fmaxf(z, 0.0f);
    }
    float z = b3[0];
#pragma unroll
    for (int j = 0; j < 3; j++) z += h2[j] * W3[j];

    out[rb * CB + cb] = 1.0f / (1.0f + expf(-z));

    g_B[rb * CB + cb] = 0.0f;          // restore invariant for next replay

    if (rb == 0 && out_size >= RB * CB + 2 * (RB + 1)) {
        out[RB * CB + cb]                 = (float)g_rcum[cb];
        out[RB * CB + (RB + 1) + cb]      = (float)g_ccum[cb];
        if (cb == 0) {
            out[RB * CB + RB]             = (float)g_rcum[RB];
            out[RB * CB + (RB + 1) + CB]  = (float)g_ccum[CB];
        }
    }
}

// ---------------------------------------------------------------------------
extern "C" void kernel_launch(void* const* d_in, const int* in_sizes, int n_in,
                              void* d_out, int out_size) {
    const float* X       = (const float*)d_in[0];
    const int*   row_ids = (const int*)d_in[1];
    const int*   col_ids = (const int*)d_in[2];
    const float* W1      = (const float*)d_in[3];
    const float* b1      = (const float*)d_in[4];
    const float* W2      = (const float*)d_in[5];
    const float* b2      = (const float*)d_in[6];
    const float* W3      = (const float*)d_in[7];
    const float* b3      = (const float*)d_in[8];
    float* out = (float*)d_out;

    k_colsum<<<GRIDC, 256>>>(X, row_ids, col_ids);
    k_final<<<RB, CB>>>(W1, b1, W2, b2, W3, b3, out, out_size);
}

// round 6
// speedup vs baseline: 1.6435x; 1.6435x over previous
#include <cuda_runtime.h>

#define NR 8192
#define NT 8192
#define RB 64
#define CB 64
#define NF (NT / 4)        // 2048 float4 per row

// Scratch (device globals — recomputed every launch, no replay state)
__device__ float4 g_S1[2][RB * NF];   // 2 half-slabs of row-block col sums, 4 MB
__device__ int    g_rcum[RB + 1];
__device__ int    g_ccum[CB + 1];

// ---------------------------------------------------------------------------
// Warp-collective lower bound: first i in [0, NR] with ids[i] >= b
// (ids sorted ascending). 3 ballot rounds: step 256 -> 8 -> 1.
// ---------------------------------------------------------------------------
__device__ __forceinline__ int warp_lb(const int* __restrict__ ids, int b, int lane) {
    int start = 0;
    {
        bool pred = ids[lane << 8] >= b;
        unsigned m = __ballot_sync(0xFFFFFFFFu, pred);
        int cf = (m == 0u) ? 32 : (__ffs(m) - 1);
        start = (cf == 0) ? 0 : (((cf - 1) << 8) + 1);
    }
    {
        int i = start + (lane << 3);
        bool pred = (i >= NR) ? true : (ids[i] >= b);
        unsigned m = __ballot_sync(0xFFFFFFFFu, pred);
        int cf = (m == 0u) ? 32 : (__ffs(m) - 1);
        if (cf > 0) start += ((cf - 1) << 3) + 1;
    }
    {
        int i = start + lane;
        bool pred = (i >= NR) ? true : (ids[i] >= b);
        unsigned m = __ballot_sync(0xFFFFFFFFu, pred);
        int cf = (m == 0u) ? 32 : (__ffs(m) - 1);
        return start + cf;
    }
}

// ---------------------------------------------------------------------------
// k_main: the 256 MB pass, logic-free hot loop.
// CTA = (rb, tile, half): sums rows of its half of row-block rb over a
// 1024-col panel (thread = one float4 column). Plain stores to its own slab.
// CTAs 1024/1025 publish rcum/ccum via transition scans (overlapped).
// ---------------------------------------------------------------------------
__global__ __launch_bounds__(256) void k_main(const float* __restrict__ X,
                                              const int* __restrict__ row_ids,
                                              const int* __restrict__ col_ids) {
    const int bx  = blockIdx.x;
    const int tid = threadIdx.x;

    if (bx >= RB * 16) {                 // boundary-publishing CTAs
        if (bx == RB * 16) {
            for (int i = tid; i < NR; i += 256) {
                int cur  = row_ids[i];
                int prev = i ? row_ids[i - 1] : -1;
                for (int b = prev; b < cur; b++) g_rcum[b + 1] = i;
            }
            if (tid == 0) { g_rcum[0] = 0; g_rcum[RB] = NR; }
        } else {
            for (int i = tid; i < NT; i += 256) {
                int cur  = col_ids[i];
                int prev = i ? col_ids[i - 1] : -1;
                for (int b = prev; b < cur; b++) g_ccum[b + 1] = i;
            }
            if (tid == 0) { g_ccum[0] = 0; g_ccum[CB] = NT; }
        }
        return;
    }

    const int rb   = bx >> 4;
    const int sub  = bx & 15;
    const int tile = sub >> 1;
    const int half = sub & 1;
    const int lane = tid & 31;
    const int w    = tid >> 5;

    __shared__ int sb[2];
    if (w == 0) { int v = warp_lb(row_ids, rb,     lane); if (lane == 0) sb[0] = v; }
    if (w == 1) { int v = warp_lb(row_ids, rb + 1, lane); if (lane == 0) sb[1] = v; }
    __syncthreads();
    const int r0rb = sb[0], r1rb = sb[1];
    const int mid  = r0rb + ((r1rb - r0rb) >> 1);
    const int r0   = half ? mid : r0rb;
    const int r1   = half ? r1rb : mid;

    const int fcol = (tile << 8) + tid;                 // float4 column 0..2047
    const float4* p = (const float4*)X + (size_t)r0 * NF + fcol;

    float4 a0 = make_float4(0.f, 0.f, 0.f, 0.f);
    float4 a1 = make_float4(0.f, 0.f, 0.f, 0.f);
    int r = r0;
    for (; r + 8 <= r1; r += 8) {                       // 8 LDG.128 in flight
        float4 q0 = p[0 * NF], q1 = p[1 * NF], q2 = p[2 * NF], q3 = p[3 * NF];
        float4 q4 = p[4 * NF], q5 = p[5 * NF], q6 = p[6 * NF], q7 = p[7 * NF];
        a0.x += q0.x; a0.y += q0.y; a0.z += q0.z; a0.w += q0.w;
        a1.x += q4.x; a1.y += q4.y; a1.z += q4.z; a1.w += q4.w;
        a0.x += q1.x; a0.y += q1.y; a0.z += q1.z; a0.w += q1.w;
        a1.x += q5.x; a1.y += q5.y; a1.z += q5.z; a1.w += q5.w;
        a0.x += q2.x; a0.y += q2.y; a0.z += q2.z; a0.w += q2.w;
        a1.x += q6.x; a1.y += q6.y; a1.z += q6.z; a1.w += q6.w;
        a0.x += q3.x; a0.y += q3.y; a0.z += q3.z; a0.w += q3.w;
        a1.x += q7.x; a1.y += q7.y; a1.z += q7.z; a1.w += q7.w;
        p += 8 * NF;
    }
    for (; r < r1; r++) {
        float4 q = p[0];
        a0.x += q.x; a0.y += q.y; a0.z += q.z; a0.w += q.w;
        p += NF;
    }
    a0.x += a1.x; a0.y += a1.y; a0.z += a1.z; a0.w += a1.w;

    g_S1[half][rb * NF + fcol] = a0;                    // plain store, no race
}

// ---------------------------------------------------------------------------
// k_tail: per row-block, combine the two slabs (32 KB), segment-reduce over
// col-blocks via the proven swizzle-staged walk, block mean, 1->3->3->1 ReLU
// MLP, sigmoid, tail cumsum outputs. Grid: 64 CTAs x 256 threads.
// ---------------------------------------------------------------------------
__global__ __launch_bounds__(256) void k_tail(const float* __restrict__ W1, const float* __restrict__ b1,
                                              const float* __restrict__ W2, const float* __restrict__ b2,
                                              const float* __restrict__ W3, const float* __restrict__ b3,
                                              float* __restrict__ out, int out_size) {
    __shared__ float4 sbuf[8][256];     // 32 KB
    __shared__ float  wsum[8][CB];
    __shared__ int    scum[CB + 1];
    __shared__ int    srcum[RB + 1];

    const int tid  = threadIdx.x;
    const int lane = tid & 31;
    const int w    = tid >> 5;
    const int rb   = blockIdx.x;

    if (tid <= CB) { scum[tid] = g_ccum[tid]; srcum[tid] = g_rcum[tid]; }
    for (int i = lane; i < CB; i += 32) wsum[w][i] = 0.0f;
    __syncthreads();

    // stage combined slabs, swizzled (conflict-free STS.128 / LDS.128)
    const float4* s0 = &g_S1[0][rb * NF];
    const float4* s1 = &g_S1[1][rb * NF];
#pragma unroll
    for (int s = 0; s < 8; s++) {
        int idx = (w << 8) + (s << 5) + lane;
        float4 qa = s0[idx], qb = s1[idx];
        qa.x += qb.x; qa.y += qb.y; qa.z += qb.z; qa.w += qb.w;
        int f = lane + (s << 5);
        sbuf[w][f ^ ((f >> 3) & 7)] = qa;
    }
    __syncwarp();

    // per-lane contiguous 32-col segment walk
    const int c0 = (w << 10) + (lane << 5);
    int lo = 0, hi = CB;
    while (lo < hi) {
        int mid = (lo + hi + 1) >> 1;
        if (scum[mid] <= c0) lo = mid; else hi = mid - 1;
    }
    int cb = lo;
    int nb = scum[cb + 1];
    float acc = 0.0f;
#pragma unroll
    for (int j = 0; j < 8; j++) {
        int f = (lane << 3) + j;
        float4 q = sbuf[w][f ^ (lane & 7)];
        int c = c0 + (j << 2);
        if (c + 4 <= nb) {
            acc += (q.x + q.y) + (q.z + q.w);
        } else {
            float e[4] = {q.x, q.y, q.z, q.w};
#pragma unroll
            for (int k = 0; k < 4; k++) {
                while (c + k >= nb) {
                    if (acc != 0.0f) atomicAdd(&wsum[w][cb], acc);
                    acc = 0.0f;
                    cb++;
                    nb = scum[cb + 1];
                }
                acc += e[k];
            }
        }
    }
    if (acc != 0.0f) atomicAdd(&wsum[w][cb], acc);
    __syncthreads();

    if (tid < CB) {
        float s = 0.0f;
#pragma unroll
        for (int q = 0; q < 8; q++) s += wsum[q][tid];

        const float rcount = (float)(srcum[rb + 1] - srcum[rb]);
        const float ccount = (float)(scum[tid + 1] - scum[tid]);
        const float x = s / (rcount * ccount);

        float h1[3], h2[3];
#pragma unroll
        for (int k = 0; k < 3; k++) h1[k] = fmaxf(x * W1[k] + b1[k], 0.0f);
#pragma unroll
        for (int j = 0; j < 3; j++) {
            float z = b2[j];
#pragma unroll
            for (int k = 0; k < 3; k++) z += h1[k] * W2[k * 3 + j];
            h2[j] = fmaxf(z, 0.0f);
        }
        float z = b3[0];
#pragma unroll
        for (int j = 0; j < 3; j++) z += h2[j] * W3[j];

        out[rb * CB + tid] = 1.0f / (1.0f + expf(-z));
    }

    if (rb == 0 && out_size >= RB * CB + 2 * (RB + 1) && tid <= RB) {
        out[RB * CB + tid]            = (float)srcum[tid];
        out[RB * CB + (RB + 1) + tid] = (float)scum[tid];
    }
}

// ---------------------------------------------------------------------------
extern "C" void kernel_launch(void* const* d_in, const int* in_sizes, int n_in,
                              void* d_out, int out_size) {
    const float* X       = (const float*)d_in[0];
    const int*   row_ids = (const int*)d_in[1];
    const int*   col_ids = (const int*)d_in[2];
    const float* W1      = (const float*)d_in[3];
    const float* b1      = (const float*)d_in[4];
    const float* W2      = (const float*)d_in[5];
    const float* b2      = (const float*)d_in[6];
    const float* W3      = (const float*)d_in[7];
    const float* b3      = (const float*)d_in[8];
    float* out = (float*)d_out;

    k_main<<<RB * 16 + 2, 256>>>(X, row_ids, col_ids);
    k_tail<<<RB, 256>>>(W1, b1, W2, b2, W3, b3, out, out_size);
}